// round 10
// baseline (speedup 1.0000x reference)
#include <cuda_runtime.h>
#include <cstdint>

// Problem constants
#define BB 512
#define TT 1024
#define DD 64
#define HH 128
#define GG 384   // 3*H
#define NTHR 768

// w_ih transposed to [col][row] so a thread's 4 consecutive rows are one 16B load
__device__ float g_wihT[DD][GG];

// ---------- packed fp32x2 helpers ----------
__device__ __forceinline__ unsigned long long ffma2(unsigned long long a,
                                                    unsigned long long b,
                                                    unsigned long long c) {
    unsigned long long d;
    asm("fma.rn.f32x2 %0, %1, %2, %3;" : "=l"(d) : "l"(a), "l"(b), "l"(c));
    return d;
}
__device__ __forceinline__ float f2sum(unsigned long long v) {
    float lo, hi;
    asm("mov.b64 {%0, %1}, %2;" : "=f"(lo), "=f"(hi) : "l"(v));
    return lo + hi;
}
__device__ __forceinline__ float2 f2unpack(unsigned long long v) {
    float lo, hi;
    asm("mov.b64 {%0, %1}, %2;" : "=f"(lo), "=f"(hi) : "l"(v));
    return make_float2(lo, hi);
}
__device__ __forceinline__ unsigned long long dup2(float v) {
    unsigned long long d;
    asm("mov.b64 %0, {%1, %1};" : "=l"(d) : "f"(v));
    return d;
}
__device__ __forceinline__ float tanh_fast(float x) {
    float y;
    asm("tanh.approx.f32 %0, %1;" : "=f"(y) : "f"(x));
    return y;
}
__device__ __forceinline__ float sigmoid_fast(float x) {
    return fmaf(tanh_fast(0.5f * x), 0.5f, 0.5f);
}

// ============================================================================
// Tiny one-time kernel: transpose w_ih [384][64] -> g_wihT [64][384]
// ============================================================================
__global__ void transpose_wih(const float* __restrict__ w_ih) {
    int i = blockIdx.x * blockDim.x + threadIdx.x;
    if (i < GG * DD) {
        int row = i / DD, col = i % DD;  // coalesced read
        g_wihT[col][row] = w_ih[i];
    }
}

// ============================================================================
// Fused persistent GRU: xg computed on the fly each step (no g_xg scratch).
// 128 CTAs x 4 batch rows, 768 threads. Thread (sw = tid/96, q = tid%96)
// owns gate rows 4q..4q+3; w_hh k-cols [16sw,+16) in regs (R9 geometry);
// w_ih k-cols [8sw,+8) streamed from L1 (g_wihT, coalesced LDG.128).
// P_s[sw][b][0..384) = combined xg+hg for r,z rows / hg for n rows;
// P_s[sw][b][384..512) = xn partials (n-gate needs xn outside r*hn).
// ============================================================================
__global__ void __launch_bounds__(NTHR, 1)
gru_fused(const float* __restrict__ x,
          const float* __restrict__ mask,
          const float* __restrict__ w_hh,
          const float* __restrict__ b_ih,
          const float* __restrict__ b_hh,
          const float* __restrict__ Wo,
          const float* __restrict__ bo,
          float* __restrict__ out) {
    __shared__ __align__(16) float h_s[4][HH];        // 2 KB
    __shared__ __align__(16) float P_s[8][4][512];    // 64 KB
    __shared__ __align__(16) float xT[2][DD][4];      // 2 KB, [parity][col][b]
    __shared__ float brz_s[2 * HH];                   // b_ih+b_hh (r,z)
    __shared__ float bhn_s[HH];                       // b_hh (n)
    __shared__ float bxn_s[HH];                       // b_ih (n)
    __shared__ float wo_s[2][HH];
    __shared__ float m_s[4];

    const int tid  = threadIdx.x;
    const int lane = tid & 31;
    const int sw   = tid / 96;        // k-split 0..7 (warp-uniform, 96=3 warps)
    const int q    = tid - sw * 96;   // rows 4q..4q+3
    const int b0   = blockIdx.x * 4;

    for (int i = tid; i < 4 * HH; i += NTHR) (&h_s[0][0])[i] = 0.0f;
    for (int i = tid; i < 2 * HH; i += NTHR) {
        (&wo_s[0][0])[i] = Wo[i];
        brz_s[i] = b_ih[i] + b_hh[i];
    }
    for (int i = tid; i < HH; i += NTHR) {
        bhn_s[i] = b_hh[2 * HH + i];
        bxn_s[i] = b_ih[2 * HH + i];
    }
    // preload x(t=0) into xT[0]: tid<256 -> (c = tid>>2, b = tid&3)
    if (tid < 256) {
        int c = tid >> 2, b = tid & 3;
        xT[0][c][b] = x[((size_t)(b0 + b) * TT) * DD + c];
    }

    // w_hh: rows 4q..4q+3, cols [16sw,+16) -> 32 ULL (64 regs)
    const int coff = 16 * sw;
    unsigned long long wq[32];
#pragma unroll
    for (int r = 0; r < 4; r++) {
        const unsigned long long* wp = reinterpret_cast<const unsigned long long*>(
            w_hh + (size_t)(4 * q + r) * HH + coff);
#pragma unroll
        for (int j = 0; j < 8; j++) wq[r * 8 + j] = wp[j];
    }

    const int cb = (tid >> 7) & 3;
    const int cj = tid & 127;
    const bool is_cell = tid < 512;
    const int xslot = (q < 64) ? 4 * q : 4 * q + 128;  // xg store column

    const float* mp = mask + (size_t)(b0 + (tid & 3)) * TT;
    const float bo0 = bo[0], bo1 = bo[1];

    __syncthreads();

    for (int t = 0; t < TT; t++) {
        const int p = t & 1;

        // ---- prefetch x(t+1) + mask into regs (hidden under compute) ----
        float xnext = 0.0f;
        if (tid < 256) {
            int c = tid >> 2, b = tid & 3;
            int tn = (t + 1 < TT) ? t + 1 : t;
            xnext = x[((size_t)(b0 + b) * TT + tn) * DD + c];
        }
        if (tid < 4) m_s[tid] = mp[t];

        // ---- xg phase: rows 4q..4q+3 x cols [8sw,+8), two 2-batch passes ----
#pragma unroll
        for (int pass = 0; pass < 2; pass++) {
            unsigned long long aA01 = 0, aA23 = 0, aB01 = 0, aB23 = 0;
            const float* gw = &g_wihT[8 * sw][4 * q];
#pragma unroll
            for (int i = 0; i < 8; i++) {
                ulonglong2 wv = *reinterpret_cast<const ulonglong2*>(gw);  // LDG.128 L1
                gw += GG;
                float2 xv = *reinterpret_cast<const float2*>(
                    &xT[p][8 * sw + i][2 * pass]);       // uniform LDS.64
                unsigned long long dA = dup2(xv.x);
                unsigned long long dB = dup2(xv.y);
                aA01 = ffma2(wv.x, dA, aA01);
                aA23 = ffma2(wv.y, dA, aA23);
                aB01 = ffma2(wv.x, dB, aB01);
                aB23 = ffma2(wv.y, dB, aB23);
            }
            float2 a01 = f2unpack(aA01), a23 = f2unpack(aA23);
            *reinterpret_cast<float4*>(&P_s[sw][2 * pass][xslot]) =
                make_float4(a01.x, a01.y, a23.x, a23.y);
            float2 b01 = f2unpack(aB01), b23 = f2unpack(aB23);
            *reinterpret_cast<float4*>(&P_s[sw][2 * pass + 1][xslot]) =
                make_float4(b01.x, b01.y, b23.x, b23.y);
        }

        // ---- h matvec: rows 4q..4q+3 x cols [16sw,+16); RMW-combine for rz ----
#pragma unroll
        for (int b = 0; b < 4; b++) {
            const ulonglong2* hp =
                reinterpret_cast<const ulonglong2*>(&h_s[b][0] + coff);
            unsigned long long a0 = 0, a1 = 0, a2 = 0, a3 = 0;
#pragma unroll
            for (int i = 0; i < 4; i++) {
                ulonglong2 v = hp[i];   // warp-uniform 16B LDS
                a0 = ffma2(wq[2 * i],      v.x, a0);
                a0 = ffma2(wq[2 * i + 1],  v.y, a0);
                a1 = ffma2(wq[8 + 2 * i],  v.x, a1);
                a1 = ffma2(wq[9 + 2 * i],  v.y, a1);
                a2 = ffma2(wq[16 + 2 * i], v.x, a2);
                a2 = ffma2(wq[17 + 2 * i], v.y, a2);
                a3 = ffma2(wq[24 + 2 * i], v.x, a3);
                a3 = ffma2(wq[25 + 2 * i], v.y, a3);
            }
            float4 hv = make_float4(f2sum(a0), f2sum(a1), f2sum(a2), f2sum(a3));
            float4* slot = reinterpret_cast<float4*>(&P_s[sw][b][4 * q]);
            if (q < 64) {  // warp-uniform predicate: combine with xg partial
                float4 xg = *slot;
                hv.x += xg.x; hv.y += xg.y; hv.z += xg.z; hv.w += xg.w;
            }
            *slot = hv;
        }
        __syncthreads();

        // ---- gate phase (warps 0-15) + x(t+1) staging ----
        if (is_cell) {
            float sr = brz_s[cj];
            float sz = brz_s[cj + HH];
            float hn = bhn_s[cj];
            float xn = bxn_s[cj];
#pragma unroll
            for (int k = 0; k < 8; k++) {
                sr += P_s[k][cb][cj];
                sz += P_s[k][cb][cj + 128];
                hn += P_s[k][cb][cj + 256];
                xn += P_s[k][cb][cj + 384];
            }
            float r  = sigmoid_fast(sr);
            float z  = sigmoid_fast(sz);
            float n  = tanh_fast(fmaf(r, hn, xn));
            float ho = h_s[cb][cj];
            float hnew = fmaf(z, ho - n, n);        // (1-z)*n + z*ho
            float m  = m_s[cb];
            h_s[cb][cj] = fmaf(m, hnew - ho, ho);   // m*hnew + (1-m)*ho
        }
        if (tid < 256) {  // stage x(t+1): writes xT[p^1], read after next barrier
            int c = tid >> 2, b = tid & 3;
            xT[p ^ 1][c][b] = xnext;
        }
        __syncthreads();

        // ---- logits on warps 16-23 (overlap next step's matvec) ----
        if (tid >= 512) {
            int w = (tid - 512) >> 5;
            int b = w >> 1, o = w & 1;
            float pv = 0.0f;
#pragma unroll
            for (int qq = 0; qq < 4; qq++)
                pv = fmaf(h_s[b][lane + 32 * qq], wo_s[o][lane + 32 * qq], pv);
#pragma unroll
            for (int off = 16; off; off >>= 1)
                pv += __shfl_down_sync(0xffffffffu, pv, off);
            if (lane == 0)
                out[(((size_t)(b0 + b)) * TT + t) * 2 + o] = pv + (o ? bo1 : bo0);
        }
    }
}

// ============================================================================
extern "C" void kernel_launch(void* const* d_in, const int* in_sizes, int n_in,
                              void* d_out, int out_size) {
    const float* x    = (const float*)d_in[0];
    const float* mask = (const float*)d_in[1];
    const float* w_ih = (const float*)d_in[2];
    const float* w_hh = (const float*)d_in[3];
    const float* b_ih = (const float*)d_in[4];
    const float* b_hh = (const float*)d_in[5];
    const float* Wo   = (const float*)d_in[6];
    const float* bo   = (const float*)d_in[7];
    float* out = (float*)d_out;

    transpose_wih<<<(GG * DD + 255) / 256, 256>>>(w_ih);
    gru_fused<<<BB / 4, NTHR>>>(x, mask, w_hh, b_ih, b_hh, Wo, bo, out);
}

// round 11
// speedup vs baseline: 1.0053x; 1.0053x over previous
#include <cuda_runtime.h>
#include <cstdint>

// Problem constants
#define BB 512
#define TT 1024
#define DD 64
#define HH 128
#define GG 384   // 3*H
#define NTHR 768

// w_ih transposed to [col][row] so a thread's 4 consecutive rows are one 16B load
__device__ float g_wihT[DD][GG];

// ---------- packed fp32x2 helpers ----------
__device__ __forceinline__ unsigned long long ffma2(unsigned long long a,
                                                    unsigned long long b,
                                                    unsigned long long c) {
    unsigned long long d;
    asm("fma.rn.f32x2 %0, %1, %2, %3;" : "=l"(d) : "l"(a), "l"(b), "l"(c));
    return d;
}
__device__ __forceinline__ float f2sum(unsigned long long v) {
    float lo, hi;
    asm("mov.b64 {%0, %1}, %2;" : "=f"(lo), "=f"(hi) : "l"(v));
    return lo + hi;
}
__device__ __forceinline__ float2 f2unpack(unsigned long long v) {
    float lo, hi;
    asm("mov.b64 {%0, %1}, %2;" : "=f"(lo), "=f"(hi) : "l"(v));
    return make_float2(lo, hi);
}
__device__ __forceinline__ unsigned long long dup2(float v) {
    unsigned long long d;
    asm("mov.b64 %0, {%1, %1};" : "=l"(d) : "f"(v));
    return d;
}
__device__ __forceinline__ float tanh_fast(float x) {
    float y;
    asm("tanh.approx.f32 %0, %1;" : "=f"(y) : "f"(x));
    return y;
}
__device__ __forceinline__ float sigmoid_fast(float x) {
    return fmaf(tanh_fast(0.5f * x), 0.5f, 0.5f);
}

// ============================================================================
// Tiny one-time kernel: transpose w_ih [384][64] -> g_wihT [64][384]
// ============================================================================
__global__ void transpose_wih(const float* __restrict__ w_ih) {
    int i = blockIdx.x * blockDim.x + threadIdx.x;
    if (i < GG * DD) {
        int row = i / DD, col = i % DD;  // coalesced read
        g_wihT[col][row] = w_ih[i];
    }
}

// ============================================================================
// Fused persistent GRU (R10 structure, x-prefetch coalescing FIXED).
// 128 CTAs x 4 batch rows, 768 threads. Thread (sw = tid/96, q = tid%96)
// owns gate rows 4q..4q+3; w_hh k-cols [16sw,+16) in regs; w_ih k-cols
// [8sw,+8) from L1-resident g_wihT (coalesced LDG.128, loop-invariant addrs).
// x(t+1) prefetched COALESCED: thread tid<256 -> (b = tid>>6, c = tid&63),
// 4 contiguous 256B rows (2 sectors/warp) instead of 32 scattered sectors.
// ============================================================================
__global__ void __launch_bounds__(NTHR, 1)
gru_fused(const float* __restrict__ x,
          const float* __restrict__ mask,
          const float* __restrict__ w_hh,
          const float* __restrict__ b_ih,
          const float* __restrict__ b_hh,
          const float* __restrict__ Wo,
          const float* __restrict__ bo,
          float* __restrict__ out) {
    __shared__ __align__(16) float h_s[4][HH];        // 2 KB
    __shared__ __align__(16) float P_s[8][4][512];    // 64 KB
    __shared__ __align__(16) float xT[2][DD][4];      // 2 KB, [parity][col][b]
    __shared__ float brz_s[2 * HH];                   // b_ih+b_hh (r,z)
    __shared__ float bhn_s[HH];                       // b_hh (n)
    __shared__ float bxn_s[HH];                       // b_ih (n)
    __shared__ float wo_s[2][HH];
    __shared__ float m_s[4];

    const int tid  = threadIdx.x;
    const int lane = tid & 31;
    const int sw   = tid / 96;        // k-split 0..7 (warp-uniform, 96=3 warps)
    const int q    = tid - sw * 96;   // rows 4q..4q+3
    const int b0   = blockIdx.x * 4;

    // coalesced x-prefetch coords (tid < 256): batch row b, column c
    const int pxb = tid >> 6;         // 0..3
    const int pxc = tid & 63;         // 0..63

    for (int i = tid; i < 4 * HH; i += NTHR) (&h_s[0][0])[i] = 0.0f;
    for (int i = tid; i < 2 * HH; i += NTHR) {
        (&wo_s[0][0])[i] = Wo[i];
        brz_s[i] = b_ih[i] + b_hh[i];
    }
    for (int i = tid; i < HH; i += NTHR) {
        bhn_s[i] = b_hh[2 * HH + i];
        bxn_s[i] = b_ih[2 * HH + i];
    }
    // preload x(t=0): fully coalesced (4 contiguous rows of 256B)
    if (tid < 256) {
        xT[0][pxc][pxb] = x[((size_t)(b0 + pxb) * TT) * DD + pxc];
    }

    // w_hh: rows 4q..4q+3, cols [16sw,+16) -> 32 ULL (64 regs)
    const int coff = 16 * sw;
    unsigned long long wq[32];
#pragma unroll
    for (int r = 0; r < 4; r++) {
        const unsigned long long* wp = reinterpret_cast<const unsigned long long*>(
            w_hh + (size_t)(4 * q + r) * HH + coff);
#pragma unroll
        for (int j = 0; j < 8; j++) wq[r * 8 + j] = wp[j];
    }

    const int cb = (tid >> 7) & 3;
    const int cj = tid & 127;
    const bool is_cell = tid < 512;
    const int xslot = (q < 64) ? 4 * q : 4 * q + 128;  // xg store column

    const float* mp = mask + (size_t)(b0 + (tid & 3)) * TT;
    const float bo0 = bo[0], bo1 = bo[1];

    __syncthreads();

    for (int t = 0; t < TT; t++) {
        const int p = t & 1;

        // ---- prefetch x(t+1) (COALESCED) + mask; hidden under compute ----
        float xnext = 0.0f;
        if (tid < 256) {
            int tn = (t + 1 < TT) ? t + 1 : t;
            xnext = x[((size_t)(b0 + pxb) * TT + tn) * DD + pxc];
        }
        if (tid < 4) m_s[tid] = mp[t];

        // ---- xg phase: rows 4q..4q+3 x cols [8sw,+8), two 2-batch passes ----
#pragma unroll
        for (int pass = 0; pass < 2; pass++) {
            unsigned long long aA01 = 0, aA23 = 0, aB01 = 0, aB23 = 0;
            const float* gw = &g_wihT[8 * sw][4 * q];
#pragma unroll
            for (int i = 0; i < 8; i++) {
                ulonglong2 wv = *reinterpret_cast<const ulonglong2*>(gw);  // L1 LDG.128
                gw += GG;
                float2 xv = *reinterpret_cast<const float2*>(
                    &xT[p][8 * sw + i][2 * pass]);       // uniform LDS.64
                unsigned long long dA = dup2(xv.x);
                unsigned long long dB = dup2(xv.y);
                aA01 = ffma2(wv.x, dA, aA01);
                aA23 = ffma2(wv.y, dA, aA23);
                aB01 = ffma2(wv.x, dB, aB01);
                aB23 = ffma2(wv.y, dB, aB23);
            }
            float2 a01 = f2unpack(aA01), a23 = f2unpack(aA23);
            *reinterpret_cast<float4*>(&P_s[sw][2 * pass][xslot]) =
                make_float4(a01.x, a01.y, a23.x, a23.y);
            float2 b01 = f2unpack(aB01), b23 = f2unpack(aB23);
            *reinterpret_cast<float4*>(&P_s[sw][2 * pass + 1][xslot]) =
                make_float4(b01.x, b01.y, b23.x, b23.y);
        }

        // ---- h matvec: rows 4q..4q+3 x cols [16sw,+16); RMW-combine for rz ----
#pragma unroll
        for (int b = 0; b < 4; b++) {
            const ulonglong2* hp =
                reinterpret_cast<const ulonglong2*>(&h_s[b][0] + coff);
            unsigned long long a0 = 0, a1 = 0, a2 = 0, a3 = 0;
#pragma unroll
            for (int i = 0; i < 4; i++) {
                ulonglong2 v = hp[i];   // warp-uniform 16B LDS
                a0 = ffma2(wq[2 * i],      v.x, a0);
                a0 = ffma2(wq[2 * i + 1],  v.y, a0);
                a1 = ffma2(wq[8 + 2 * i],  v.x, a1);
                a1 = ffma2(wq[9 + 2 * i],  v.y, a1);
                a2 = ffma2(wq[16 + 2 * i], v.x, a2);
                a2 = ffma2(wq[17 + 2 * i], v.y, a2);
                a3 = ffma2(wq[24 + 2 * i], v.x, a3);
                a3 = ffma2(wq[25 + 2 * i], v.y, a3);
            }
            float4 hv = make_float4(f2sum(a0), f2sum(a1), f2sum(a2), f2sum(a3));
            float4* slot = reinterpret_cast<float4*>(&P_s[sw][b][4 * q]);
            if (q < 64) {  // warp-uniform predicate: combine with xg partial
                float4 xg = *slot;
                hv.x += xg.x; hv.y += xg.y; hv.z += xg.z; hv.w += xg.w;
            }
            *slot = hv;
        }
        __syncthreads();

        // ---- gate phase (warps 0-15) + x(t+1) staging ----
        if (is_cell) {
            float sr = brz_s[cj];
            float sz = brz_s[cj + HH];
            float hn = bhn_s[cj];
            float xn = bxn_s[cj];
#pragma unroll
            for (int k = 0; k < 8; k++) {
                sr += P_s[k][cb][cj];
                sz += P_s[k][cb][cj + 128];
                hn += P_s[k][cb][cj + 256];
                xn += P_s[k][cb][cj + 384];
            }
            float r  = sigmoid_fast(sr);
            float z  = sigmoid_fast(sz);
            float n  = tanh_fast(fmaf(r, hn, xn));
            float ho = h_s[cb][cj];
            float hnew = fmaf(z, ho - n, n);        // (1-z)*n + z*ho
            float m  = m_s[cb];
            h_s[cb][cj] = fmaf(m, hnew - ho, ho);   // m*hnew + (1-m)*ho
        }
        if (tid < 256) {  // stage x(t+1): writes xT[p^1], read after next barrier
            xT[p ^ 1][pxc][pxb] = xnext;
        }
        __syncthreads();

        // ---- logits on warps 16-23 (overlap next step's compute) ----
        if (tid >= 512) {
            int w = (tid - 512) >> 5;
            int b = w >> 1, o = w & 1;
            float pv = 0.0f;
#pragma unroll
            for (int qq = 0; qq < 4; qq++)
                pv = fmaf(h_s[b][lane + 32 * qq], wo_s[o][lane + 32 * qq], pv);
#pragma unroll
            for (int off = 16; off; off >>= 1)
                pv += __shfl_down_sync(0xffffffffu, pv, off);
            if (lane == 0)
                out[(((size_t)(b0 + b)) * TT + t) * 2 + o] = pv + (o ? bo1 : bo0);
        }
    }
}

// ============================================================================
extern "C" void kernel_launch(void* const* d_in, const int* in_sizes, int n_in,
                              void* d_out, int out_size) {
    const float* x    = (const float*)d_in[0];
    const float* mask = (const float*)d_in[1];
    const float* w_ih = (const float*)d_in[2];
    const float* w_hh = (const float*)d_in[3];
    const float* b_ih = (const float*)d_in[4];
    const float* b_hh = (const float*)d_in[5];
    const float* Wo   = (const float*)d_in[6];
    const float* bo   = (const float*)d_in[7];
    float* out = (float*)d_out;

    transpose_wih<<<(GG * DD + 255) / 256, 256>>>(w_ih);
    gru_fused<<<BB / 4, NTHR>>>(x, mask, w_hh, b_ih, b_hh, Wo, bo, out);
}

// round 13
// speedup vs baseline: 1.7206x; 1.7115x over previous
#include <cuda_runtime.h>
#include <cuda_bf16.h>
#include <cstdint>

// Problem constants
#define BB 512
#define TT 1024
#define DD 64
#define HH 128
#define GG 384   // 3*H
#define NTHR 768

// Scratch for precomputed input gates, layout [b][t][g]
__device__ float g_xg[(size_t)BB * TT * GG];

// ---------- packed fp32x2 helpers ----------
__device__ __forceinline__ unsigned long long ffma2(unsigned long long a,
                                                    unsigned long long b,
                                                    unsigned long long c) {
    unsigned long long d;
    asm("fma.rn.f32x2 %0, %1, %2, %3;" : "=l"(d) : "l"(a), "l"(b), "l"(c));
    return d;
}
__device__ __forceinline__ float f2sum(unsigned long long v) {
    float lo, hi;
    asm("mov.b64 {%0, %1}, %2;" : "=f"(lo), "=f"(hi) : "l"(v));
    return lo + hi;
}
__device__ __forceinline__ float tanh_fast(float x) {
    float y;
    asm("tanh.approx.f32 %0, %1;" : "=f"(y) : "f"(x));
    return y;
}
__device__ __forceinline__ float sigmoid_fast(float x) {
    return fmaf(tanh_fast(0.5f * x), 0.5f, 0.5f);
}

// ---------- mma.sync / ldmatrix helpers (compute_103-safe, sm_80 PTX) ----------
__device__ __forceinline__ uint32_t smem_u32(const void* p) {
    uint32_t a;
    asm("{ .reg .u64 t; cvta.to.shared.u64 t, %1; cvt.u32.u64 %0, t; }"
        : "=r"(a) : "l"(p));
    return a;
}
__device__ __forceinline__ void ldm_x4(uint32_t& r0, uint32_t& r1,
                                       uint32_t& r2, uint32_t& r3, uint32_t a) {
    asm volatile("ldmatrix.sync.aligned.m8n8.x4.shared.b16 {%0,%1,%2,%3}, [%4];"
                 : "=r"(r0), "=r"(r1), "=r"(r2), "=r"(r3) : "r"(a));
}
__device__ __forceinline__ void ldm_x2(uint32_t& r0, uint32_t& r1, uint32_t a) {
    asm volatile("ldmatrix.sync.aligned.m8n8.x2.shared.b16 {%0,%1}, [%2];"
                 : "=r"(r0), "=r"(r1) : "r"(a));
}
__device__ __forceinline__ void mma_bf16(float* c, const uint32_t* a,
                                         const uint32_t* b) {
    asm volatile(
        "mma.sync.aligned.m16n8k16.row.col.f32.bf16.bf16.f32 "
        "{%0,%1,%2,%3}, {%4,%5,%6,%7}, {%8,%9}, {%0,%1,%2,%3};"
        : "+f"(c[0]), "+f"(c[1]), "+f"(c[2]), "+f"(c[3])
        : "r"(a[0]), "r"(a[1]), "r"(a[2]), "r"(a[3]), "r"(b[0]), "r"(b[1]));
}

// smem layout (byte offsets; row stride 72 bf16 = 144B, conflict-free ldmatrix)
#define XS_AHI   0
#define XS_ALO   18432                      // 128*144
#define XS_BHI   36864
#define XS_BLO   92160                      // + 384*144
#define XS_BIAS  147456
#define XS_TOTAL (XS_BIAS + GG * 4 + 128)

// ============================================================================
// Kernel 1: xg via HMMA (mma.sync m16n8k16 bf16, hi/lo split, 3 passes).
// Grid 4096 = (b, 8 tiles of 128 tokens); 256 threads (8 warps).
// Warp wi owns gates [48wi, 48wi+48) — B fragments preloaded to regs once —
// and loops 8 m-tiles of 16 tokens (A via ldmatrix.x4 from padded smem).
// ============================================================================
__global__ void __launch_bounds__(256, 1)
xg_mma(const float* __restrict__ x,
       const float* __restrict__ w_ih,
       const float* __restrict__ b_ih) {
    extern __shared__ __align__(128) char sm[];
    const uint32_t smb = smem_u32(sm);
    const int tid  = threadIdx.x;
    const int wi   = tid >> 5;
    const int lane = tid & 31;

    const int b  = blockIdx.x >> 3;
    const int t0 = (blockIdx.x & 7) << 7;

    // ---- stage A: x[b][t0..+128][0..64] -> bf16 hi/lo, stride 72 ----
    for (int i = tid; i < 128 * DD; i += 256) {
        int tok = i >> 6, c = i & 63;
        float v = x[((size_t)b * TT + t0 + tok) * DD + c];
        __nv_bfloat16 hi = __float2bfloat16_rn(v);
        __nv_bfloat16 lo = __float2bfloat16_rn(v - __bfloat162float(hi));
        int off = (tok * 72 + c) * 2;
        *reinterpret_cast<__nv_bfloat16*>(sm + XS_AHI + off) = hi;
        *reinterpret_cast<__nv_bfloat16*>(sm + XS_ALO + off) = lo;
    }
    // ---- stage B: w_ih[0..384][0..64] -> bf16 hi/lo, stride 72 ----
    for (int i = tid; i < GG * DD; i += 256) {
        int n = i >> 6, k = i & 63;
        float v = w_ih[(size_t)n * DD + k];
        __nv_bfloat16 hi = __float2bfloat16_rn(v);
        __nv_bfloat16 lo = __float2bfloat16_rn(v - __bfloat162float(hi));
        int off = (n * 72 + k) * 2;
        *reinterpret_cast<__nv_bfloat16*>(sm + XS_BHI + off) = hi;
        *reinterpret_cast<__nv_bfloat16*>(sm + XS_BLO + off) = lo;
    }
    for (int i = tid; i < GG; i += 256)
        reinterpret_cast<float*>(sm + XS_BIAS)[i] = b_ih[i];
    __syncthreads();

    // ---- preload B fragments: 6 n-tiles x 4 k-steps x {hi,lo} ----
    uint32_t bh[6][4][2], bl[6][4][2];
    {
        const int brow = 48 * wi + (lane & 7);
        const int bcol = ((lane >> 3) & 1) * 16;  // bytes
#pragma unroll
        for (int j = 0; j < 6; j++)
#pragma unroll
            for (int kk = 0; kk < 4; kk++) {
                uint32_t a = smb + XS_BHI + (brow + 8 * j) * 144 + bcol + kk * 32;
                ldm_x2(bh[j][kk][0], bh[j][kk][1], a);
                a = smb + XS_BLO + (brow + 8 * j) * 144 + bcol + kk * 32;
                ldm_x2(bl[j][kk][0], bl[j][kk][1], a);
            }
    }
    // bias pairs for this warp's 6 n-tiles
    float2 bias[6];
    {
        const int c0 = 2 * (lane & 3);
#pragma unroll
        for (int j = 0; j < 6; j++)
            bias[j] = *reinterpret_cast<const float2*>(
                sm + XS_BIAS + (48 * wi + 8 * j + c0) * 4);
    }

    const int arow = lane & 15;
    const int acol = ((lane >> 4) & 1) * 16;  // bytes
    const int drow = lane >> 2;
    const int dcol = 2 * (lane & 3);

#pragma unroll 1
    for (int m = 0; m < 8; m++) {
        // A fragments for tokens [16m, 16m+16): 4 k-steps x {hi,lo}
        uint32_t ah[4][4], al[4][4];
#pragma unroll
        for (int kk = 0; kk < 4; kk++) {
            uint32_t a = smb + XS_AHI + (16 * m + arow) * 144 + acol + kk * 32;
            ldm_x4(ah[kk][0], ah[kk][1], ah[kk][2], ah[kk][3], a);
            a = smb + XS_ALO + (16 * m + arow) * 144 + acol + kk * 32;
            ldm_x4(al[kk][0], al[kk][1], al[kk][2], al[kk][3], a);
        }
#pragma unroll
        for (int j = 0; j < 6; j++) {
            float acc[4] = {bias[j].x, bias[j].y, bias[j].x, bias[j].y};
#pragma unroll
            for (int kk = 0; kk < 4; kk++) mma_bf16(acc, ah[kk], bh[j][kk]);
#pragma unroll
            for (int kk = 0; kk < 4; kk++) mma_bf16(acc, al[kk], bh[j][kk]);
#pragma unroll
            for (int kk = 0; kk < 4; kk++) mma_bf16(acc, ah[kk], bl[j][kk]);

            const size_t base =
                ((size_t)b * TT + t0 + 16 * m + drow) * GG + 48 * wi + 8 * j + dcol;
            *reinterpret_cast<float2*>(g_xg + base) = make_float2(acc[0], acc[1]);
            *reinterpret_cast<float2*>(g_xg + base + 8 * GG) =
                make_float2(acc[2], acc[3]);
        }
    }
}

// ============================================================================
// Kernel 2: persistent GRU — R9 structure (best: 2261us), xg layout [b][t][g].
// ============================================================================
__global__ void __launch_bounds__(NTHR, 1)
gru_kernel(const float* __restrict__ mask,
           const float* __restrict__ w_hh,
           const float* __restrict__ b_hh,
           const float* __restrict__ Wo,
           const float* __restrict__ bo,
           float* __restrict__ out) {
    __shared__ __align__(16) float h_s[4][HH];
    __shared__ __align__(16) float P_s[8][4][GG];
    __shared__ float bh_s[GG];
    __shared__ float m_s[4];
    __shared__ float wo_s[2][HH];

    const int tid  = threadIdx.x;
    const int lane = tid & 31;
    const int sw   = tid / 96;
    const int q    = tid - sw * 96;
    const int b0   = blockIdx.x * 4;

    for (int i = tid; i < 4 * HH; i += NTHR) (&h_s[0][0])[i] = 0.0f;
    for (int i = tid; i < 2 * HH; i += NTHR) (&wo_s[0][0])[i] = Wo[i];
    for (int i = tid; i < GG; i += NTHR) bh_s[i] = b_hh[i];

    const int coff = 16 * sw;
    unsigned long long wq[32];
#pragma unroll
    for (int r = 0; r < 4; r++) {
        const unsigned long long* wp = reinterpret_cast<const unsigned long long*>(
            w_hh + (size_t)(4 * q + r) * HH + coff);
#pragma unroll
        for (int j = 0; j < 8; j++) wq[r * 8 + j] = wp[j];
    }

    const int cb = (tid >> 7) & 3;
    const int cj = tid & 127;
    const bool is_cell = tid < 512;

    const float* xg_cell = g_xg + (size_t)(b0 + cb) * TT * GG + cj;
    const float* mp = mask + (size_t)(b0 + (tid & 3)) * TT;
    const float bo0 = bo[0], bo1 = bo[1];

    __syncthreads();

    for (int t = 0; t < TT; t++) {
        float xr_v = 0.f, xz_v = 0.f, xn_v = 0.f;
        if (is_cell) {
            xr_v = xg_cell[0];
            xz_v = xg_cell[HH];
            xn_v = xg_cell[2 * HH];
        }
        if (tid < 4) m_s[tid] = mp[t];

#pragma unroll
        for (int b = 0; b < 4; b++) {
            const ulonglong2* hp =
                reinterpret_cast<const ulonglong2*>(&h_s[b][0] + coff);
            unsigned long long a0 = 0, a1 = 0, a2 = 0, a3 = 0;
#pragma unroll
            for (int i = 0; i < 4; i++) {
                ulonglong2 v = hp[i];
                a0 = ffma2(wq[2 * i],      v.x, a0);
                a0 = ffma2(wq[2 * i + 1],  v.y, a0);
                a1 = ffma2(wq[8 + 2 * i],  v.x, a1);
                a1 = ffma2(wq[9 + 2 * i],  v.y, a1);
                a2 = ffma2(wq[16 + 2 * i], v.x, a2);
                a2 = ffma2(wq[17 + 2 * i], v.y, a2);
                a3 = ffma2(wq[24 + 2 * i], v.x, a3);
                a3 = ffma2(wq[25 + 2 * i], v.y, a3);
            }
            *reinterpret_cast<float4*>(&P_s[sw][b][4 * q]) =
                make_float4(f2sum(a0), f2sum(a1), f2sum(a2), f2sum(a3));
        }
        __syncthreads();

        if (is_cell) {
            float sr = xr_v + bh_s[cj];
            float sz = xz_v + bh_s[cj + HH];
            float sn = bh_s[cj + 2 * HH];
#pragma unroll
            for (int k = 0; k < 8; k++) {
                sr += P_s[k][cb][cj];
                sz += P_s[k][cb][cj + HH];
                sn += P_s[k][cb][cj + 2 * HH];
            }
            float r  = sigmoid_fast(sr);
            float z  = sigmoid_fast(sz);
            float n  = tanh_fast(fmaf(r, sn, xn_v));
            float ho = h_s[cb][cj];
            float hnew = fmaf(z, ho - n, n);
            float m  = m_s[cb];
            h_s[cb][cj] = fmaf(m, hnew - ho, ho);
        }
        __syncthreads();

        if (tid >= 512) {
            int w = (tid - 512) >> 5;
            int b = w >> 1, o = w & 1;
            float pv = 0.0f;
#pragma unroll
            for (int qq = 0; qq < 4; qq++)
                pv = fmaf(h_s[b][lane + 32 * qq], wo_s[o][lane + 32 * qq], pv);
#pragma unroll
            for (int off = 16; off; off >>= 1)
                pv += __shfl_down_sync(0xffffffffu, pv, off);
            if (lane == 0)
                out[(((size_t)(b0 + b)) * TT + t) * 2 + o] = pv + (o ? bo1 : bo0);
        }

        xg_cell += GG;
    }
}

// ============================================================================
extern "C" void kernel_launch(void* const* d_in, const int* in_sizes, int n_in,
                              void* d_out, int out_size) {
    const float* x    = (const float*)d_in[0];
    const float* mask = (const float*)d_in[1];
    const float* w_ih = (const float*)d_in[2];
    const float* w_hh = (const float*)d_in[3];
    const float* b_ih = (const float*)d_in[4];
    const float* b_hh = (const float*)d_in[5];
    const float* Wo   = (const float*)d_in[6];
    const float* bo   = (const float*)d_in[7];
    float* out = (float*)d_out;

    cudaFuncSetAttribute(xg_mma, cudaFuncAttributeMaxDynamicSharedMemorySize,
                         XS_TOTAL);
    xg_mma<<<BB * 8, 256, XS_TOTAL>>>(x, w_ih, b_ih);
    gru_kernel<<<BB / 4, NTHR>>>(mask, w_hh, b_hh, Wo, bo, out);
}

// round 14
// speedup vs baseline: 1.7598x; 1.0228x over previous
#include <cuda_runtime.h>
#include <cuda_bf16.h>
#include <cstdint>

// Problem constants
#define BB 512
#define TT 1024
#define DD 64
#define HH 128
#define GG 384   // 3*H
#define NTHR 768

// Scratch for precomputed input gates, layout [b][t][g]
__device__ float g_xg[(size_t)BB * TT * GG];

// ---------- packed fp32x2 helpers ----------
__device__ __forceinline__ unsigned long long ffma2(unsigned long long a,
                                                    unsigned long long b,
                                                    unsigned long long c) {
    unsigned long long d;
    asm("fma.rn.f32x2 %0, %1, %2, %3;" : "=l"(d) : "l"(a), "l"(b), "l"(c));
    return d;
}
__device__ __forceinline__ float f2sum(unsigned long long v) {
    float lo, hi;
    asm("mov.b64 {%0, %1}, %2;" : "=f"(lo), "=f"(hi) : "l"(v));
    return lo + hi;
}
__device__ __forceinline__ float tanh_fast(float x) {
    float y;
    asm("tanh.approx.f32 %0, %1;" : "=f"(y) : "f"(x));
    return y;
}
__device__ __forceinline__ float sigmoid_fast(float x) {
    return fmaf(tanh_fast(0.5f * x), 0.5f, 0.5f);
}

// ---------- mma.sync / ldmatrix helpers (compute_103-safe, sm_80 PTX) ----------
__device__ __forceinline__ uint32_t smem_u32(const void* p) {
    uint32_t a;
    asm("{ .reg .u64 t; cvta.to.shared.u64 t, %1; cvt.u32.u64 %0, t; }"
        : "=r"(a) : "l"(p));
    return a;
}
__device__ __forceinline__ void ldm_x4(uint32_t& r0, uint32_t& r1,
                                       uint32_t& r2, uint32_t& r3, uint32_t a) {
    asm volatile("ldmatrix.sync.aligned.m8n8.x4.shared.b16 {%0,%1,%2,%3}, [%4];"
                 : "=r"(r0), "=r"(r1), "=r"(r2), "=r"(r3) : "r"(a));
}
__device__ __forceinline__ void ldm_x2(uint32_t& r0, uint32_t& r1, uint32_t a) {
    asm volatile("ldmatrix.sync.aligned.m8n8.x2.shared.b16 {%0,%1}, [%2];"
                 : "=r"(r0), "=r"(r1) : "r"(a));
}
__device__ __forceinline__ void mma_bf16(float* c, const uint32_t* a,
                                         const uint32_t* b) {
    asm volatile(
        "mma.sync.aligned.m16n8k16.row.col.f32.bf16.bf16.f32 "
        "{%0,%1,%2,%3}, {%4,%5,%6,%7}, {%8,%9}, {%0,%1,%2,%3};"
        : "+f"(c[0]), "+f"(c[1]), "+f"(c[2]), "+f"(c[3])
        : "r"(a[0]), "r"(a[1]), "r"(a[2]), "r"(a[3]), "r"(b[0]), "r"(b[1]));
}

// smem layout (byte offsets; row stride 72 bf16 = 144B, conflict-free ldmatrix)
#define XS_AHI   0
#define XS_ALO   18432                      // 128*144
#define XS_BHI   36864
#define XS_BLO   92160                      // + 384*144
#define XS_BIAS  147456
#define XS_TOTAL (XS_BIAS + GG * 4 + 128)

// ============================================================================
// Kernel 1: xg via HMMA, B-staging amortized 4x.
// Grid 1024 = (b, 2 halves of 512 tokens); 256 threads (8 warps).
// Per CTA: stage B (hi/lo) + preload B fragments ONCE, then 4 chunks of
// 128 tokens (A restaged per chunk). Fragment math identical to R13.
// ============================================================================
__global__ void __launch_bounds__(256, 1)
xg_mma(const float* __restrict__ x,
       const float* __restrict__ w_ih,
       const float* __restrict__ b_ih) {
    extern __shared__ __align__(128) char sm[];
    const uint32_t smb = smem_u32(sm);
    const int tid  = threadIdx.x;
    const int wi   = tid >> 5;
    const int lane = tid & 31;

    const int b    = blockIdx.x >> 1;
    const int tbase = (blockIdx.x & 1) << 9;   // 0 or 512

    // ---- stage B once: w_ih[0..384][0..64] -> bf16 hi/lo, stride 72 ----
    for (int i = tid; i < GG * DD; i += 256) {
        int n = i >> 6, k = i & 63;
        float v = w_ih[(size_t)n * DD + k];
        __nv_bfloat16 hi = __float2bfloat16_rn(v);
        __nv_bfloat16 lo = __float2bfloat16_rn(v - __bfloat162float(hi));
        int off = (n * 72 + k) * 2;
        *reinterpret_cast<__nv_bfloat16*>(sm + XS_BHI + off) = hi;
        *reinterpret_cast<__nv_bfloat16*>(sm + XS_BLO + off) = lo;
    }
    for (int i = tid; i < GG; i += 256)
        reinterpret_cast<float*>(sm + XS_BIAS)[i] = b_ih[i];
    __syncthreads();

    // ---- preload B fragments once: 6 n-tiles x 4 k-steps x {hi,lo} ----
    uint32_t bh[6][4][2], bl[6][4][2];
    {
        const int brow = 48 * wi + (lane & 7);
        const int bcol = ((lane >> 3) & 1) * 16;  // bytes
#pragma unroll
        for (int j = 0; j < 6; j++)
#pragma unroll
            for (int kk = 0; kk < 4; kk++) {
                uint32_t a = smb + XS_BHI + (brow + 8 * j) * 144 + bcol + kk * 32;
                ldm_x2(bh[j][kk][0], bh[j][kk][1], a);
                a = smb + XS_BLO + (brow + 8 * j) * 144 + bcol + kk * 32;
                ldm_x2(bl[j][kk][0], bl[j][kk][1], a);
            }
    }
    float2 bias[6];
    {
        const int c0 = 2 * (lane & 3);
#pragma unroll
        for (int j = 0; j < 6; j++)
            bias[j] = *reinterpret_cast<const float2*>(
                sm + XS_BIAS + (48 * wi + 8 * j + c0) * 4);
    }

    const int arow = lane & 15;
    const int acol = ((lane >> 4) & 1) * 16;  // bytes
    const int drow = lane >> 2;
    const int dcol = 2 * (lane & 3);

#pragma unroll 1
    for (int ch = 0; ch < 4; ch++) {
        const int t0 = tbase + (ch << 7);

        // ---- stage A chunk: x[b][t0..+128][0..64] -> bf16 hi/lo ----
        for (int i = tid; i < 128 * DD; i += 256) {
            int tok = i >> 6, c = i & 63;
            float v = x[((size_t)b * TT + t0 + tok) * DD + c];
            __nv_bfloat16 hi = __float2bfloat16_rn(v);
            __nv_bfloat16 lo = __float2bfloat16_rn(v - __bfloat162float(hi));
            int off = (tok * 72 + c) * 2;
            *reinterpret_cast<__nv_bfloat16*>(sm + XS_AHI + off) = hi;
            *reinterpret_cast<__nv_bfloat16*>(sm + XS_ALO + off) = lo;
        }
        __syncthreads();

#pragma unroll 1
        for (int m = 0; m < 8; m++) {
            uint32_t ah[4][4], al[4][4];
#pragma unroll
            for (int kk = 0; kk < 4; kk++) {
                uint32_t a = smb + XS_AHI + (16 * m + arow) * 144 + acol + kk * 32;
                ldm_x4(ah[kk][0], ah[kk][1], ah[kk][2], ah[kk][3], a);
                a = smb + XS_ALO + (16 * m + arow) * 144 + acol + kk * 32;
                ldm_x4(al[kk][0], al[kk][1], al[kk][2], al[kk][3], a);
            }
#pragma unroll
            for (int j = 0; j < 6; j++) {
                float acc[4] = {bias[j].x, bias[j].y, bias[j].x, bias[j].y};
#pragma unroll
                for (int kk = 0; kk < 4; kk++) mma_bf16(acc, ah[kk], bh[j][kk]);
#pragma unroll
                for (int kk = 0; kk < 4; kk++) mma_bf16(acc, al[kk], bh[j][kk]);
#pragma unroll
                for (int kk = 0; kk < 4; kk++) mma_bf16(acc, ah[kk], bl[j][kk]);

                const size_t base =
                    ((size_t)b * TT + t0 + 16 * m + drow) * GG + 48 * wi + 8 * j + dcol;
                *reinterpret_cast<float2*>(g_xg + base) =
                    make_float2(acc[0], acc[1]);
                *reinterpret_cast<float2*>(g_xg + base + 8 * GG) =
                    make_float2(acc[2], acc[3]);
            }
        }
        __syncthreads();  // all warps done with A before restaging
    }
}

// ============================================================================
// Kernel 2: persistent GRU — FROZEN (R13, 2203us best).
// ============================================================================
__global__ void __launch_bounds__(NTHR, 1)
gru_kernel(const float* __restrict__ mask,
           const float* __restrict__ w_hh,
           const float* __restrict__ b_hh,
           const float* __restrict__ Wo,
           const float* __restrict__ bo,
           float* __restrict__ out) {
    __shared__ __align__(16) float h_s[4][HH];
    __shared__ __align__(16) float P_s[8][4][GG];
    __shared__ float bh_s[GG];
    __shared__ float m_s[4];
    __shared__ float wo_s[2][HH];

    const int tid  = threadIdx.x;
    const int lane = tid & 31;
    const int sw   = tid / 96;
    const int q    = tid - sw * 96;
    const int b0   = blockIdx.x * 4;

    for (int i = tid; i < 4 * HH; i += NTHR) (&h_s[0][0])[i] = 0.0f;
    for (int i = tid; i < 2 * HH; i += NTHR) (&wo_s[0][0])[i] = Wo[i];
    for (int i = tid; i < GG; i += NTHR) bh_s[i] = b_hh[i];

    const int coff = 16 * sw;
    unsigned long long wq[32];
#pragma unroll
    for (int r = 0; r < 4; r++) {
        const unsigned long long* wp = reinterpret_cast<const unsigned long long*>(
            w_hh + (size_t)(4 * q + r) * HH + coff);
#pragma unroll
        for (int j = 0; j < 8; j++) wq[r * 8 + j] = wp[j];
    }

    const int cb = (tid >> 7) & 3;
    const int cj = tid & 127;
    const bool is_cell = tid < 512;

    const float* xg_cell = g_xg + (size_t)(b0 + cb) * TT * GG + cj;
    const float* mp = mask + (size_t)(b0 + (tid & 3)) * TT;
    const float bo0 = bo[0], bo1 = bo[1];

    __syncthreads();

    for (int t = 0; t < TT; t++) {
        float xr_v = 0.f, xz_v = 0.f, xn_v = 0.f;
        if (is_cell) {
            xr_v = xg_cell[0];
            xz_v = xg_cell[HH];
            xn_v = xg_cell[2 * HH];
        }
        if (tid < 4) m_s[tid] = mp[t];

#pragma unroll
        for (int b = 0; b < 4; b++) {
            const ulonglong2* hp =
                reinterpret_cast<const ulonglong2*>(&h_s[b][0] + coff);
            unsigned long long a0 = 0, a1 = 0, a2 = 0, a3 = 0;
#pragma unroll
            for (int i = 0; i < 4; i++) {
                ulonglong2 v = hp[i];
                a0 = ffma2(wq[2 * i],      v.x, a0);
                a0 = ffma2(wq[2 * i + 1],  v.y, a0);
                a1 = ffma2(wq[8 + 2 * i],  v.x, a1);
                a1 = ffma2(wq[9 + 2 * i],  v.y, a1);
                a2 = ffma2(wq[16 + 2 * i], v.x, a2);
                a2 = ffma2(wq[17 + 2 * i], v.y, a2);
                a3 = ffma2(wq[24 + 2 * i], v.x, a3);
                a3 = ffma2(wq[25 + 2 * i], v.y, a3);
            }
            *reinterpret_cast<float4*>(&P_s[sw][b][4 * q]) =
                make_float4(f2sum(a0), f2sum(a1), f2sum(a2), f2sum(a3));
        }
        __syncthreads();

        if (is_cell) {
            float sr = xr_v + bh_s[cj];
            float sz = xz_v + bh_s[cj + HH];
            float sn = bh_s[cj + 2 * HH];
#pragma unroll
            for (int k = 0; k < 8; k++) {
                sr += P_s[k][cb][cj];
                sz += P_s[k][cb][cj + HH];
                sn += P_s[k][cb][cj + 2 * HH];
            }
            float r  = sigmoid_fast(sr);
            float z  = sigmoid_fast(sz);
            float n  = tanh_fast(fmaf(r, sn, xn_v));
            float ho = h_s[cb][cj];
            float hnew = fmaf(z, ho - n, n);
            float m  = m_s[cb];
            h_s[cb][cj] = fmaf(m, hnew - ho, ho);
        }
        __syncthreads();

        if (tid >= 512) {
            int w = (tid - 512) >> 5;
            int b = w >> 1, o = w & 1;
            float pv = 0.0f;
#pragma unroll
            for (int qq = 0; qq < 4; qq++)
                pv = fmaf(h_s[b][lane + 32 * qq], wo_s[o][lane + 32 * qq], pv);
#pragma unroll
            for (int off = 16; off; off >>= 1)
                pv += __shfl_down_sync(0xffffffffu, pv, off);
            if (lane == 0)
                out[(((size_t)(b0 + b)) * TT + t) * 2 + o] = pv + (o ? bo1 : bo0);
        }

        xg_cell += GG;
    }
}

// ============================================================================
extern "C" void kernel_launch(void* const* d_in, const int* in_sizes, int n_in,
                              void* d_out, int out_size) {
    const float* x    = (const float*)d_in[0];
    const float* mask = (const float*)d_in[1];
    const float* w_ih = (const float*)d_in[2];
    const float* w_hh = (const float*)d_in[3];
    const float* b_ih = (const float*)d_in[4];
    const float* b_hh = (const float*)d_in[5];
    const float* Wo   = (const float*)d_in[6];
    const float* bo   = (const float*)d_in[7];
    float* out = (float*)d_out;

    cudaFuncSetAttribute(xg_mma, cudaFuncAttributeMaxDynamicSharedMemorySize,
                         XS_TOTAL);
    xg_mma<<<BB * 2, 256, XS_TOTAL>>>(x, w_ih, b_ih);
    gru_kernel<<<BB / 4, NTHR>>>(mask, w_hh, b_hh, Wo, bo, out);
}